// round 1
// baseline (speedup 1.0000x reference)
#include <cuda_runtime.h>
#include <cuda_bf16.h>
#include <cstdint>

// ----------------------------------------------------------------------------
// Problem constants (all static; index arrays in the reference are derivable)
//   B = 8192, K = 512, L = 10752 literals, C = 2688 conjunctions, F = 256
//   Literal triples of 12: depths (2,4,6). Formula group g = f>>6 has
//   n_conj = 6+3g contiguous conjunctions; conj_start(f) = 96*g*(g+3) + (f&63)*n_conj.
// ----------------------------------------------------------------------------
#define BATCH   8192
#define KDIM    512
#define LDIM    10752
#define CDIM    2688
#define FDIM    256

// GEMM tiling
#define BM 128
#define BN 96       // 8 triples = 24 conjunctions per tile (triple-aligned)
#define BK 16
#define TM 8
#define TN 6
#define NTHREADS 256

// conj scratch [B, C] and transposed mu [K, F]
__device__ float g_conj[(size_t)BATCH * CDIM];
__device__ float g_muT[KDIM * FDIM];

// ----------------------------------------------------------------------------
// prep: transpose mu [F,K] -> g_muT [K,F]
// ----------------------------------------------------------------------------
__global__ void prep_mu_kernel(const float* __restrict__ mu) {
    int i = blockIdx.x * blockDim.x + threadIdx.x;   // 131072 total
    if (i < FDIM * KDIM) {
        int f = i / KDIM, k = i % KDIM;
        g_muT[k * FDIM + f] = mu[i];
    }
}

// ----------------------------------------------------------------------------
// Stage 2: fused literal GEMM + tanh + conjunction reduction
//   literals = tanh(x @ (W*M) + bias); conj = tanh(seg_sum - d + 1.5)
//   Writes g_conj[b][c].
// ----------------------------------------------------------------------------
__global__ __launch_bounds__(NTHREADS, 2)
void fused_gemm_dnf_kernel(const float* __restrict__ x,
                           const float* __restrict__ w,
                           const float* __restrict__ msk,
                           const float* __restrict__ bias)
{
    extern __shared__ float sm[];
    // GEMM buffers (union'd with epilogue tile):
    //   As[2][BK][BM] = 4096 floats, Bs[2][BK][BN] = 3072 floats
    float* As = sm;
    float* Bs = sm + 2 * BK * BM;

    const int tid = threadIdx.x;
    const int bx = blockIdx.x;   // L tile: 0..111
    const int by = blockIdx.y;   // B tile: 0..63
    const int ty = tid >> 4;     // 0..15
    const int tx = tid & 15;     // 0..15

    const float* xg = x   + (size_t)(by * BM) * KDIM;
    const float* wg = w   + bx * BN;
    const float* mg = msk + bx * BN;

    float acc[TM][TN];
#pragma unroll
    for (int i = 0; i < TM; i++)
#pragma unroll
        for (int j = 0; j < TN; j++) acc[i][j] = 0.f;

    // A loads: 128 rows x 16 k, float4. thread -> rows {tid>>2, tid>>2 + 64}, k-cols (tid&3)*4
    const int arow = tid >> 2;
    const int acol = (tid & 3) * 4;
    // B loads: 16 rows x 96 cols = 768 float2; idx = tid + 256*i; r = idx/48, c2 = idx%48
    float4 aR0, aR1;
    float2 bR[3];

#define LOAD_G(kc)                                                                 \
    {                                                                              \
        aR0 = *(const float4*)(xg + (size_t)arow * KDIM + (kc) * BK + acol);       \
        aR1 = *(const float4*)(xg + (size_t)(arow + 64) * KDIM + (kc) * BK + acol);\
        _Pragma("unroll")                                                          \
        for (int i = 0; i < 3; i++) {                                              \
            int idx = tid + 256 * i;                                               \
            int r = idx / 48, c2 = idx % 48;                                       \
            size_t go = (size_t)((kc) * BK + r) * LDIM + c2 * 2;                   \
            float2 wv = *(const float2*)(wg + go);                                 \
            float2 mv = *(const float2*)(mg + go);                                 \
            bR[i].x = wv.x * mv.x; bR[i].y = wv.y * mv.y;                          \
        }                                                                          \
    }

#define STORE_S(buf)                                                               \
    {                                                                              \
        float* da = As + (buf) * BK * BM;                                          \
        da[(acol + 0) * BM + arow]      = aR0.x;                                   \
        da[(acol + 1) * BM + arow]      = aR0.y;                                   \
        da[(acol + 2) * BM + arow]      = aR0.z;                                   \
        da[(acol + 3) * BM + arow]      = aR0.w;                                   \
        da[(acol + 0) * BM + arow + 64] = aR1.x;                                   \
        da[(acol + 1) * BM + arow + 64] = aR1.y;                                   \
        da[(acol + 2) * BM + arow + 64] = aR1.z;                                   \
        da[(acol + 3) * BM + arow + 64] = aR1.w;                                   \
        float* db = Bs + (buf) * BK * BN;                                          \
        _Pragma("unroll")                                                          \
        for (int i = 0; i < 3; i++) {                                              \
            int idx = tid + 256 * i;                                               \
            int r = idx / 48, c2 = idx % 48;                                       \
            *(float2*)(db + r * BN + c2 * 2) = bR[i];                              \
        }                                                                          \
    }

    LOAD_G(0);
    STORE_S(0);
    __syncthreads();

    int buf = 0;
    const int NKC = KDIM / BK;   // 32
    for (int kc = 0; kc < NKC; kc++) {
        if (kc < NKC - 1) LOAD_G(kc + 1);
        const float* a = As + buf * BK * BM;
        const float* b = Bs + buf * BK * BN;
#pragma unroll
        for (int kk = 0; kk < BK; kk++) {
            float av[TM], bv[TN];
            float4 av0 = *(const float4*)(a + kk * BM + ty * TM);
            float4 av1 = *(const float4*)(a + kk * BM + ty * TM + 4);
            av[0]=av0.x; av[1]=av0.y; av[2]=av0.z; av[3]=av0.w;
            av[4]=av1.x; av[5]=av1.y; av[6]=av1.z; av[7]=av1.w;
            float2 bv0 = *(const float2*)(b + kk * BN + tx * TN);
            float2 bv1 = *(const float2*)(b + kk * BN + tx * TN + 2);
            float2 bv2 = *(const float2*)(b + kk * BN + tx * TN + 4);
            bv[0]=bv0.x; bv[1]=bv0.y; bv[2]=bv1.x; bv[3]=bv1.y; bv[4]=bv2.x; bv[5]=bv2.y;
#pragma unroll
            for (int i = 0; i < TM; i++)
#pragma unroll
                for (int j = 0; j < TN; j++)
                    acc[i][j] = fmaf(av[i], bv[j], acc[i][j]);
        }
        if (kc < NKC - 1) {
            STORE_S(buf ^ 1);
            __syncthreads();
            buf ^= 1;
        }
    }

    // ---------------- epilogue: tanh + conj reduce -----------------
    __syncthreads();                      // all reads of GEMM smem done
    float* Ls = sm;                       // [128][96] literal tile (48 KB)
    float bb[TN];
#pragma unroll
    for (int j = 0; j < TN; j++) bb[j] = bias[bx * BN + tx * TN + j];
#pragma unroll
    for (int i = 0; i < TM; i++)
#pragma unroll
        for (int j = 0; j < TN; j++)
            Ls[(ty * TM + i) * BN + tx * TN + j] = tanhf(acc[i][j] + bb[j]);
    __syncthreads();

    // 128 rows x 24 conj = 3072 tasks
    for (int t = tid; t < BM * 24; t += NTHREADS) {
        int c   = t % 24;
        int row = t / 24;
        int tri = c / 3, p = c % 3;
        int base = tri * 12 + p * (p + 1);     // offsets 0,2,6
        int dep  = 2 * (p + 1);                // depths  2,4,6
        float s = 0.f;
        for (int q = 0; q < dep; q++) s += Ls[row * BN + base + q];
        g_conj[(size_t)(by * BM + row) * CDIM + bx * 24 + c] = tanhf(s - (float)dep + 1.5f);
    }
#undef LOAD_G
#undef STORE_S
}

// ----------------------------------------------------------------------------
// Stage 3: conj -> formula tanh, RBF localization softmax, final product
// One CTA handles RB batch rows x all 256 formulas (thread == formula).
// ----------------------------------------------------------------------------
#define RB 16

__global__ __launch_bounds__(NTHREADS)
void finalize_kernel(const float* __restrict__ x,
                     const float* __restrict__ sigma,
                     float* __restrict__ out)
{
    __shared__ float xs[RB][KDIM];    // 32 KB
    __shared__ float xn[RB];
    __shared__ float red[8];

    const int tid = threadIdx.x;
    const int f   = tid;              // formula id
    const int r0  = blockIdx.x * RB;

    for (int i = tid; i < RB * KDIM; i += NTHREADS) {
        int r = i >> 9, k = i & (KDIM - 1);
        xs[r][k] = x[(size_t)(r0 + r) * KDIM + k];
    }
    __syncthreads();

    if (tid < RB) {
        float s = 0.f;
        for (int k = 0; k < KDIM; k++) s += xs[tid][k] * xs[tid][k];
        xn[tid] = s;
    }

    // dot products x[r] . mu[f] for all RB rows, plus ||mu_f||^2
    float acc[RB];
#pragma unroll
    for (int r = 0; r < RB; r++) acc[r] = 0.f;
    float mn = 0.f;
    for (int k4 = 0; k4 < KDIM; k4 += 4) {
        float m0 = g_muT[(k4 + 0) * FDIM + f];
        float m1 = g_muT[(k4 + 1) * FDIM + f];
        float m2 = g_muT[(k4 + 2) * FDIM + f];
        float m3 = g_muT[(k4 + 3) * FDIM + f];
        mn = fmaf(m0, m0, mn); mn = fmaf(m1, m1, mn);
        mn = fmaf(m2, m2, mn); mn = fmaf(m3, m3, mn);
#pragma unroll
        for (int r = 0; r < RB; r++) {
            float4 xv = *(const float4*)&xs[r][k4];
            float a = acc[r];
            a = fmaf(xv.x, m0, a);
            a = fmaf(xv.y, m1, a);
            a = fmaf(xv.z, m2, a);
            a = fmaf(xv.w, m3, a);
            acc[r] = a;
        }
    }
    __syncthreads();   // xn ready

    const float sig   = sigma[f];
    const float inv2s = 0.5f / (sig * sig);
    const int   g     = f >> 6;
    const int   nconj = 6 + 3 * g;
    const int   cstart = 96 * g * (g + 3) + (f & 63) * nconj;
    const int   lane = tid & 31, warp = tid >> 5;

    for (int r = 0; r < RB; r++) {
        // dnnf
        const float* cp = g_conj + (size_t)(r0 + r) * CDIM + cstart;
        float s = 0.f;
        for (int q = 0; q < nconj; q++) s += cp[q];
        float dnnf = tanhf(s + (float)nconj - 1.5f);

        // localization logit: T * exp(-0.5*||x-mu||^2 / sigma^2), T = 2
        float sq = xn[r] - 2.f * acc[r] + mn;
        float logit = 2.0f * expf(-sq * inv2s);
        float e = expf(logit);          // logits in (0,2]; no max-shift needed

        // block sum over 256 threads
        float v = e;
#pragma unroll
        for (int off = 16; off > 0; off >>= 1)
            v += __shfl_xor_sync(0xffffffffu, v, off);
        if (lane == 0) red[warp] = v;
        __syncthreads();
        float tot = red[0] + red[1] + red[2] + red[3] +
                    red[4] + red[5] + red[6] + red[7];
        out[(size_t)(r0 + r) * FDIM + f] = dnnf * (e / tot);
        __syncthreads();                // protect red[] for next row
    }
}

// ----------------------------------------------------------------------------
// launch
// ----------------------------------------------------------------------------
extern "C" void kernel_launch(void* const* d_in, const int* in_sizes, int n_in,
                              void* d_out, int out_size)
{
    const float* x     = (const float*)d_in[0];
    const float* w     = (const float*)d_in[1];
    const float* msk   = (const float*)d_in[2];
    const float* bias  = (const float*)d_in[3];
    const float* mu    = (const float*)d_in[4];
    const float* sigma = (const float*)d_in[5];
    float* out = (float*)d_out;

    prep_mu_kernel<<<(FDIM * KDIM + 255) / 256, 256>>>(mu);

    dim3 grid(LDIM / BN, BATCH / BM);   // (112, 64)
    fused_gemm_dnf_kernel<<<grid, NTHREADS, 48 * 1024>>>(x, w, msk, bias);

    finalize_kernel<<<BATCH / RB, NTHREADS>>>(x, sigma, out);
}

// round 3
// speedup vs baseline: 2.6296x; 2.6296x over previous
#include <cuda_runtime.h>
#include <cuda_bf16.h>
#include <cstdint>

// ----------------------------------------------------------------------------
// B = 8192, K = 512, L = 10752 literals, C = 2688 conj, F = 256
// tf32 mma.sync GEMM (plain sm_103 target: no tcgen05 available).
// ----------------------------------------------------------------------------
#define BATCH   8192
#define KDIM    512
#define LDIM    10752
#define CDIM    2688
#define FDIM    256

#define BM 128
#define BN 192          // 16 triples = 48 conjunctions (triple-aligned)
#define BK 32
#define NTHREADS 512    // 16 warps: 4 (m) x 4 (n), warp tile 32 x 48
#define STAGE   40960   // (128+192)*32*4 bytes
#define BOFF    16384   // B tile offset within stage
#define SM_BIAS (3 * STAGE)
#define SMEM_NEED (SM_BIAS + 768)
#define LPITCH  200     // epilogue literal tile pitch (floats)

// scratch
__device__ float g_A[(size_t)BATCH * KDIM];   // tf32-rounded x
__device__ float g_B[(size_t)LDIM * KDIM];    // tf32-rounded (w*mask)^T, [L][K]
__device__ float g_conj[(size_t)BATCH * CDIM];
__device__ float g_muT[KDIM * FDIM];

// ---------------------------------------------------------------- helpers
__device__ __forceinline__ uint32_t smem_u32(const void* p) {
    uint32_t a;
    asm("{ .reg .u64 t; cvta.to.shared.u64 t, %1; cvt.u32.u64 %0, t; }" : "=r"(a) : "l"(p));
    return a;
}
__device__ __forceinline__ float tf32r(float f) {
    float o;
    asm("cvt.rna.tf32.f32 %0, %1;" : "=f"(o) : "f"(f));
    return o;
}
__device__ __forceinline__ void cp16(uint32_t dst, const void* src) {
    asm volatile("cp.async.cg.shared.global [%0], [%1], 16;" :: "r"(dst), "l"(src) : "memory");
}
#define CP_COMMIT() asm volatile("cp.async.commit_group;" ::: "memory")
#define CP_WAIT(n)  asm volatile("cp.async.wait_group %0;" :: "n"(n) : "memory")

__device__ __forceinline__ void ldsm_x4(uint32_t addr, uint32_t r[4]) {
    asm volatile("ldmatrix.sync.aligned.m8n8.x4.shared.b16 {%0,%1,%2,%3}, [%4];"
        : "=r"(r[0]), "=r"(r[1]), "=r"(r[2]), "=r"(r[3]) : "r"(addr));
}
__device__ __forceinline__ void mma_tf32(float c[4], const uint32_t a[4],
                                         uint32_t b0, uint32_t b1) {
    asm volatile("mma.sync.aligned.m16n8k8.row.col.f32.tf32.tf32.f32 "
        "{%0,%1,%2,%3}, {%4,%5,%6,%7}, {%8,%9}, {%0,%1,%2,%3};"
        : "+f"(c[0]), "+f"(c[1]), "+f"(c[2]), "+f"(c[3])
        : "r"(a[0]), "r"(a[1]), "r"(a[2]), "r"(a[3]), "r"(b0), "r"(b1));
}

// accurate fast tanh: 1 MUFU ex2 + fast divide, ~1e-6 abs error
__device__ __forceinline__ float fast_tanh(float x) {
    float ax = fabsf(x);
    float t;
    asm("ex2.approx.f32 %0, %1;" : "=f"(t) : "f"(ax * -2.885390082f));  // e^{-2|x|}
    float r = __fdividef(1.f - t, 1.f + t);
    return copysignf(r, x);
}

// ---------------------------------------------------------------- prep kernels
__global__ void prep_mu_kernel(const float* __restrict__ mu) {
    int i = blockIdx.x * blockDim.x + threadIdx.x;
    if (i < FDIM * KDIM) {
        int f = i / KDIM, k = i % KDIM;
        g_muT[k * FDIM + f] = mu[i];
    }
}

__global__ void prep_x_kernel(const float* __restrict__ x) {
    int i = blockIdx.x * blockDim.x + threadIdx.x;   // BATCH*KDIM/4
    if (i >= BATCH * KDIM / 4) return;
    float4 v = *(const float4*)(x + (size_t)i * 4);
    v.x = tf32r(v.x); v.y = tf32r(v.y); v.z = tf32r(v.z); v.w = tf32r(v.w);
    *(float4*)(g_A + (size_t)i * 4) = v;
}

// w,m are [K][L]; produce g_B = tf32(w*m)^T as [L][K]
__global__ void prep_w_kernel(const float* __restrict__ w, const float* __restrict__ m) {
    __shared__ float s[32][33];
    int n0 = blockIdx.x * 32, k0 = blockIdx.y * 32;
    int tx = threadIdx.x, ty = threadIdx.y;
    size_t gi = (size_t)(k0 + ty) * LDIM + n0 + tx;
    s[ty][tx] = tf32r(w[gi] * m[gi]);
    __syncthreads();
    g_B[(size_t)(n0 + ty) * KDIM + k0 + tx] = s[tx][ty];
}

// ---------------------------------------------------------------- fused GEMM
__global__ __launch_bounds__(NTHREADS, 1)
void fused_gemm_dnf_kernel(const float* __restrict__ bias) {
    extern __shared__ char smp[];
    const uint32_t sb = smem_u32(smp);

    const int tid = threadIdx.x;
    const int wid = tid >> 5, lane = tid & 31;
    const int bx = blockIdx.x;   // N tile 0..55
    const int by = blockIdx.y;   // M tile 0..63
    const int warp_m = wid & 3;  // 32-row band
    const int warp_n = wid >> 2; // 48-col band

    float* sbias = (float*)(smp + SM_BIAS);
    if (tid < BN) sbias[tid] = bias[bx * BN + tid];

    const float* Ag = g_A + (size_t)(by * BM) * KDIM;
    const float* Bg = g_B + (size_t)(bx * BN) * KDIM;

    // ldmatrix per-thread address precompute
    const int q = lane >> 3, r8 = lane & 7;
    int am[2], am128[2], a7[2];
#pragma unroll
    for (int t = 0; t < 2; t++) {
        am[t] = warp_m * 32 + t * 16 + ((q & 1) << 3) + r8;
        am128[t] = am[t] * 128; a7[t] = am[t] & 7;
    }
    const int a_kadd = q >> 1;
    int bn128[3], b7[3];
#pragma unroll
    for (int i = 0; i < 3; i++) {
        int n = warp_n * 48 + i * 16 + ((q >> 1) << 3) + r8;
        bn128[i] = n * 128; b7[i] = n & 7;
    }
    const int b_kadd = q & 1;

    float c[2][6][4];
#pragma unroll
    for (int t = 0; t < 2; t++)
#pragma unroll
        for (int n = 0; n < 6; n++)
#pragma unroll
            for (int e = 0; e < 4; e++) c[t][n][e] = 0.f;

#define ISSUE(kt)                                                              \
    {                                                                          \
        const uint32_t stA = sb + ((kt) % 3) * STAGE;                          \
        _Pragma("unroll")                                                      \
        for (int j = 0; j < 2; j++) {                                          \
            int idx = tid + NTHREADS * j;                                      \
            int row = idx >> 3, ch = idx & 7;                                  \
            cp16(stA + row * 128 + ((ch ^ (row & 7)) << 4),                    \
                 Ag + (size_t)row * KDIM + (kt) * BK + ch * 4);                \
        }                                                                      \
        _Pragma("unroll")                                                      \
        for (int j = 0; j < 3; j++) {                                          \
            int idx = tid + NTHREADS * j;                                      \
            int row = idx >> 3, ch = idx & 7;                                  \
            cp16(stA + BOFF + row * 128 + ((ch ^ (row & 7)) << 4),             \
                 Bg + (size_t)row * KDIM + (kt) * BK + ch * 4);                \
        }                                                                      \
        CP_COMMIT();                                                           \
    }

    ISSUE(0);
    ISSUE(1);

    const int NKT = KDIM / BK;   // 16
    for (int kt = 0; kt < NKT; kt++) {
        CP_WAIT(1);
        __syncthreads();
        if (kt + 2 < NKT) { ISSUE(kt + 2); } else { CP_COMMIT(); }

        const uint32_t sA = sb + (kt % 3) * STAGE;
        const uint32_t sB = sA + BOFF;
#pragma unroll
        for (int ks = 0; ks < 4; ks++) {
            uint32_t af[2][4], bf[3][4];
#pragma unroll
            for (int t = 0; t < 2; t++)
                ldsm_x4(sA + am128[t] + (((2 * ks + a_kadd) ^ a7[t]) << 4), af[t]);
#pragma unroll
            for (int i = 0; i < 3; i++)
                ldsm_x4(sB + bn128[i] + (((2 * ks + b_kadd) ^ b7[i]) << 4), bf[i]);
#pragma unroll
            for (int t = 0; t < 2; t++)
#pragma unroll
                for (int i = 0; i < 3; i++) {
                    mma_tf32(c[t][2 * i + 0], af[t], bf[i][0], bf[i][1]);
                    mma_tf32(c[t][2 * i + 1], af[t], bf[i][2], bf[i][3]);
                }
        }
    }
#undef ISSUE

    CP_WAIT(0);
    __syncthreads();   // done with pipeline smem; reuse as literal tile

    // ---------------- epilogue: tanh + conj reduce ----------------
    float* Ls = (float*)smp;   // [128][LPITCH]
    const int g = lane >> 2, cc = lane & 3;
#pragma unroll
    for (int t = 0; t < 2; t++) {
        int row0 = warp_m * 32 + t * 16 + g;
#pragma unroll
        for (int i = 0; i < 3; i++)
#pragma unroll
            for (int j = 0; j < 2; j++) {
                int colb = warp_n * 48 + i * 16 + j * 8 + 2 * cc;
                int nt = 2 * i + j;
                float b0 = sbias[colb], b1 = sbias[colb + 1];
                float2 v0, v1;
                v0.x = fast_tanh(c[t][nt][0] + b0);
                v0.y = fast_tanh(c[t][nt][1] + b1);
                v1.x = fast_tanh(c[t][nt][2] + b0);
                v1.y = fast_tanh(c[t][nt][3] + b1);
                *(float2*)(Ls + row0 * LPITCH + colb) = v0;
                *(float2*)(Ls + (row0 + 8) * LPITCH + colb) = v1;
            }
    }
    __syncthreads();

    // 128 rows x 48 conj = 6144 tasks
    for (int t = tid; t < BM * 48; t += NTHREADS) {
        int ci  = t % 48;
        int row = t / 48;
        int tri = ci / 3, p = ci % 3;
        int base = tri * 12 + p * (p + 1);   // 0, 2, 6
        int dep  = 2 * (p + 1);              // 2, 4, 6
        const float* rp = Ls + row * LPITCH + base;
        float s = 0.f;
        for (int qq = 0; qq < dep; qq++) s += rp[qq];
        g_conj[(size_t)(by * BM + row) * CDIM + bx * 48 + ci] =
            fast_tanh(s - (float)dep + 1.5f);
    }
}

// ---------------------------------------------------------------- finalize
#define RB 16

__global__ __launch_bounds__(256)
void finalize_kernel(const float* __restrict__ x,
                     const float* __restrict__ sigma,
                     float* __restrict__ out)
{
    __shared__ float xs[RB][KDIM];
    __shared__ float xn[RB];
    __shared__ float red[8];

    const int tid = threadIdx.x;
    const int f   = tid;
    const int r0  = blockIdx.x * RB;

    for (int i = tid; i < RB * KDIM; i += 256) {
        int r = i >> 9, k = i & (KDIM - 1);
        xs[r][k] = x[(size_t)(r0 + r) * KDIM + k];
    }
    __syncthreads();

    if (tid < RB) {
        float s = 0.f;
        for (int k = 0; k < KDIM; k++) s += xs[tid][k] * xs[tid][k];
        xn[tid] = s;
    }

    float acc[RB];
#pragma unroll
    for (int r = 0; r < RB; r++) acc[r] = 0.f;
    float mn = 0.f;
    for (int k4 = 0; k4 < KDIM; k4 += 4) {
        float m0 = g_muT[(k4 + 0) * FDIM + f];
        float m1 = g_muT[(k4 + 1) * FDIM + f];
        float m2 = g_muT[(k4 + 2) * FDIM + f];
        float m3 = g_muT[(k4 + 3) * FDIM + f];
        mn = fmaf(m0, m0, mn); mn = fmaf(m1, m1, mn);
        mn = fmaf(m2, m2, mn); mn = fmaf(m3, m3, mn);
#pragma unroll
        for (int r = 0; r < RB; r++) {
            float4 xv = *(const float4*)&xs[r][k4];
            float a = acc[r];
            a = fmaf(xv.x, m0, a);
            a = fmaf(xv.y, m1, a);
            a = fmaf(xv.z, m2, a);
            a = fmaf(xv.w, m3, a);
            acc[r] = a;
        }
    }
    __syncthreads();

    const float sig   = sigma[f];
    const float inv2s = 0.5f / (sig * sig);
    const int   g     = f >> 6;
    const int   nconj = 6 + 3 * g;
    const int   cstart = 96 * g * (g + 3) + (f & 63) * nconj;
    const int   lane = tid & 31, warp = tid >> 5;

    for (int r = 0; r < RB; r++) {
        const float* cp = g_conj + (size_t)(r0 + r) * CDIM + cstart;
        float s = 0.f;
        for (int qd = 0; qd < nconj; qd++) s += cp[qd];
        float dnnf = tanhf(s + (float)nconj - 1.5f);

        float sq = xn[r] - 2.f * acc[r] + mn;
        float logit = 2.0f * expf(-sq * inv2s);
        float e = expf(logit);

        float v = e;
#pragma unroll
        for (int off = 16; off > 0; off >>= 1)
            v += __shfl_xor_sync(0xffffffffu, v, off);
        if (lane == 0) red[warp] = v;
        __syncthreads();
        float tot = red[0] + red[1] + red[2] + red[3] +
                    red[4] + red[5] + red[6] + red[7];
        out[(size_t)(r0 + r) * FDIM + f] = dnnf * (e / tot);
        __syncthreads();
    }
}

// ---------------------------------------------------------------- launch
extern "C" void kernel_launch(void* const* d_in, const int* in_sizes, int n_in,
                              void* d_out, int out_size)
{
    const float* x     = (const float*)d_in[0];
    const float* w     = (const float*)d_in[1];
    const float* msk   = (const float*)d_in[2];
    const float* bias  = (const float*)d_in[3];
    const float* mu    = (const float*)d_in[4];
    const float* sigma = (const float*)d_in[5];
    float* out = (float*)d_out;

    cudaFuncSetAttribute(fused_gemm_dnf_kernel,
                         cudaFuncAttributeMaxDynamicSharedMemorySize, SMEM_NEED);

    prep_mu_kernel<<<(FDIM * KDIM + 255) / 256, 256>>>(mu);
    prep_x_kernel<<<(BATCH * KDIM / 4 + 255) / 256, 256>>>(x);
    {
        dim3 g(LDIM / 32, KDIM / 32);
        dim3 b(32, 32);
        prep_w_kernel<<<g, b>>>(w, msk);
    }
    {
        dim3 grid(LDIM / BN, BATCH / BM);   // (56, 64)
        fused_gemm_dnf_kernel<<<grid, NTHREADS, SMEM_NEED>>>(bias);
    }
    finalize_kernel<<<BATCH / RB, 256>>>(x, sigma, out);
}

// round 4
// speedup vs baseline: 3.8034x; 1.4463x over previous
#include <cuda_runtime.h>
#include <cuda_fp16.h>
#include <cstdint>

// ----------------------------------------------------------------------------
// B = 8192, K = 512, L = 10752 literals, C = 2688 conj, F = 256
// fp16 mma.sync m16n8k16 GEMM (plain sm_103 target: no tcgen05 available).
// ----------------------------------------------------------------------------
#define BATCH   8192
#define KDIM    512
#define LDIM    10752
#define CDIM    2688
#define FDIM    256

#define BM 128
#define BN 192          // 16 triples = 48 conjunctions (triple-aligned)
#define BK 64           // 64 fp16 = 128 bytes per row
#define NTHREADS 512    // 16 warps: 4 (m) x 4 (n), warp tile 32 x 48
#define STAGE   40960   // (128+192)*128 bytes
#define BOFF    16384   // B tile offset within stage (128*128)
#define SM_BIAS (3 * STAGE)
#define SMEM_NEED (SM_BIAS + 768)
#define LPITCH  200     // epilogue literal tile pitch (floats)

// scratch
__device__ __half g_A[(size_t)BATCH * KDIM];   // fp16 x
__device__ __half g_B[(size_t)LDIM * KDIM];    // fp16 (w*mask)^T, [L][K]
__device__ float g_conj[(size_t)BATCH * CDIM];
__device__ float g_muT[KDIM * FDIM];

// ---------------------------------------------------------------- helpers
__device__ __forceinline__ uint32_t smem_u32(const void* p) {
    uint32_t a;
    asm("{ .reg .u64 t; cvta.to.shared.u64 t, %1; cvt.u32.u64 %0, t; }" : "=r"(a) : "l"(p));
    return a;
}
__device__ __forceinline__ void cp16(uint32_t dst, const void* src) {
    asm volatile("cp.async.cg.shared.global [%0], [%1], 16;" :: "r"(dst), "l"(src) : "memory");
}
#define CP_COMMIT() asm volatile("cp.async.commit_group;" ::: "memory")
#define CP_WAIT(n)  asm volatile("cp.async.wait_group %0;" :: "n"(n) : "memory")

__device__ __forceinline__ void ldsm_x4(uint32_t addr, uint32_t r[4]) {
    asm volatile("ldmatrix.sync.aligned.m8n8.x4.shared.b16 {%0,%1,%2,%3}, [%4];"
        : "=r"(r[0]), "=r"(r[1]), "=r"(r[2]), "=r"(r[3]) : "r"(addr));
}
__device__ __forceinline__ void mma_f16(float c[4], const uint32_t a[4],
                                        uint32_t b0, uint32_t b1) {
    asm volatile("mma.sync.aligned.m16n8k16.row.col.f32.f16.f16.f32 "
        "{%0,%1,%2,%3}, {%4,%5,%6,%7}, {%8,%9}, {%0,%1,%2,%3};"
        : "+f"(c[0]), "+f"(c[1]), "+f"(c[2]), "+f"(c[3])
        : "r"(a[0]), "r"(a[1]), "r"(a[2]), "r"(a[3]), "r"(b0), "r"(b1));
}

// accurate fast tanh: 1 MUFU ex2 + fast divide, ~1e-6 abs error
__device__ __forceinline__ float fast_tanh(float x) {
    float ax = fabsf(x);
    float t;
    asm("ex2.approx.f32 %0, %1;" : "=f"(t) : "f"(ax * -2.885390082f));  // e^{-2|x|}
    float r = __fdividef(1.f - t, 1.f + t);
    return copysignf(r, x);
}

// ---------------------------------------------------------------- prep kernels
__global__ void prep_mu_kernel(const float* __restrict__ mu) {
    int i = blockIdx.x * blockDim.x + threadIdx.x;
    if (i < FDIM * KDIM) {
        int f = i / KDIM, k = i % KDIM;
        g_muT[k * FDIM + f] = mu[i];
    }
}

__global__ void prep_x_kernel(const float* __restrict__ x) {
    int i = blockIdx.x * blockDim.x + threadIdx.x;   // BATCH*KDIM/8
    if (i >= BATCH * KDIM / 8) return;
    float4 v0 = *(const float4*)(x + (size_t)i * 8);
    float4 v1 = *(const float4*)(x + (size_t)i * 8 + 4);
    __half2 h[4];
    h[0] = __floats2half2_rn(v0.x, v0.y);
    h[1] = __floats2half2_rn(v0.z, v0.w);
    h[2] = __floats2half2_rn(v1.x, v1.y);
    h[3] = __floats2half2_rn(v1.z, v1.w);
    *(uint4*)(g_A + (size_t)i * 8) = *(uint4*)h;
}

// w,m are [K][L]; produce g_B = fp16(w*m)^T as [L][K]
__global__ void prep_w_kernel(const float* __restrict__ w, const float* __restrict__ m) {
    __shared__ float s[32][33];
    int n0 = blockIdx.x * 32, k0 = blockIdx.y * 32;
    int tx = threadIdx.x, ty = threadIdx.y;
    size_t gi = (size_t)(k0 + ty) * LDIM + n0 + tx;
    s[ty][tx] = w[gi] * m[gi];
    __syncthreads();
    g_B[(size_t)(n0 + ty) * KDIM + k0 + tx] = __float2half_rn(s[tx][ty]);
}

// ---------------------------------------------------------------- fused GEMM
__global__ __launch_bounds__(NTHREADS, 1)
void fused_gemm_dnf_kernel(const float* __restrict__ bias) {
    extern __shared__ char smp[];
    const uint32_t sb = smem_u32(smp);

    const int tid = threadIdx.x;
    const int wid = tid >> 5, lane = tid & 31;
    const int bx = blockIdx.x;   // N tile 0..55
    const int by = blockIdx.y;   // M tile 0..63
    const int warp_m = wid & 3;  // 32-row band
    const int warp_n = wid >> 2; // 48-col band

    float* sbias = (float*)(smp + SM_BIAS);
    if (tid < BN) sbias[tid] = bias[bx * BN + tid];

    const __half* Ag = g_A + (size_t)(by * BM) * KDIM;
    const __half* Bg = g_B + (size_t)(bx * BN) * KDIM;

    // ldmatrix per-thread address precompute
    // .x4 pattern: lanes 0-15 -> rows (lane&15), lanes 16-31 -> same rows, +16B chunk
    const int r16 = lane & 15, l4 = lane >> 4;
    int am128[2], a7[2];
#pragma unroll
    for (int t = 0; t < 2; t++) {
        int row = warp_m * 32 + t * 16 + r16;
        am128[t] = row * 128; a7[t] = row & 7;
    }
    int bn128[3], b7[3];
#pragma unroll
    for (int i = 0; i < 3; i++) {
        int n = warp_n * 48 + i * 16 + r16;
        bn128[i] = n * 128; b7[i] = n & 7;
    }

    float c[2][6][4];
#pragma unroll
    for (int t = 0; t < 2; t++)
#pragma unroll
        for (int n = 0; n < 6; n++)
#pragma unroll
            for (int e = 0; e < 4; e++) c[t][n][e] = 0.f;

    // loads: A 128 rows x 8 chunks = 1024 ops (2/thread), B 192 x 8 = 1536 (3/thread)
#define ISSUE(kt)                                                              \
    {                                                                          \
        const uint32_t stA = sb + ((kt) % 3) * STAGE;                          \
        _Pragma("unroll")                                                      \
        for (int j = 0; j < 2; j++) {                                          \
            int idx = tid + NTHREADS * j;                                      \
            int row = idx >> 3, ch = idx & 7;                                  \
            cp16(stA + row * 128 + ((ch ^ (row & 7)) << 4),                    \
                 Ag + (size_t)row * KDIM + (kt) * BK + ch * 8);                \
        }                                                                      \
        _Pragma("unroll")                                                      \
        for (int j = 0; j < 3; j++) {                                          \
            int idx = tid + NTHREADS * j;                                      \
            int row = idx >> 3, ch = idx & 7;                                  \
            cp16(stA + BOFF + row * 128 + ((ch ^ (row & 7)) << 4),             \
                 Bg + (size_t)row * KDIM + (kt) * BK + ch * 8);                \
        }                                                                      \
        CP_COMMIT();                                                           \
    }

    ISSUE(0);
    ISSUE(1);

    const int NKT = KDIM / BK;   // 8
    for (int kt = 0; kt < NKT; kt++) {
        CP_WAIT(1);
        __syncthreads();
        if (kt + 2 < NKT) { ISSUE(kt + 2); } else { CP_COMMIT(); }

        const uint32_t sA = sb + (kt % 3) * STAGE;
        const uint32_t sB = sA + BOFF;
#pragma unroll
        for (int ks = 0; ks < 4; ks++) {           // 4 x k16 per BK=64 chunk
            uint32_t af[2][4], bf[3][4];
            const int ch = 2 * ks + l4;
#pragma unroll
            for (int t = 0; t < 2; t++)
                ldsm_x4(sA + am128[t] + ((ch ^ a7[t]) << 4), af[t]);
#pragma unroll
            for (int i = 0; i < 3; i++)
                ldsm_x4(sB + bn128[i] + ((ch ^ b7[i]) << 4), bf[i]);
#pragma unroll
            for (int t = 0; t < 2; t++)
#pragma unroll
                for (int i = 0; i < 3; i++) {
                    // n-sub 0: regs {0,2}, n-sub 1: regs {1,3}
                    mma_f16(c[t][2 * i + 0], af[t], bf[i][0], bf[i][2]);
                    mma_f16(c[t][2 * i + 1], af[t], bf[i][1], bf[i][3]);
                }
        }
    }
#undef ISSUE

    CP_WAIT(0);
    __syncthreads();   // done with pipeline smem; reuse as literal tile

    // ---------------- epilogue: tanh + conj reduce ----------------
    float* Ls = (float*)smp;   // [128][LPITCH]
    const int g = lane >> 2, cc = lane & 3;
#pragma unroll
    for (int t = 0; t < 2; t++) {
        int row0 = warp_m * 32 + t * 16 + g;
#pragma unroll
        for (int i = 0; i < 3; i++)
#pragma unroll
            for (int j = 0; j < 2; j++) {
                int colb = warp_n * 48 + i * 16 + j * 8 + 2 * cc;
                int nt = 2 * i + j;
                float b0 = sbias[colb], b1 = sbias[colb + 1];
                float2 v0, v1;
                v0.x = fast_tanh(c[t][nt][0] + b0);
                v0.y = fast_tanh(c[t][nt][1] + b1);
                v1.x = fast_tanh(c[t][nt][2] + b0);
                v1.y = fast_tanh(c[t][nt][3] + b1);
                *(float2*)(Ls + row0 * LPITCH + colb) = v0;
                *(float2*)(Ls + (row0 + 8) * LPITCH + colb) = v1;
            }
    }
    __syncthreads();

    // 128 rows x 48 conj = 6144 tasks
    for (int t = tid; t < BM * 48; t += NTHREADS) {
        int ci  = t % 48;
        int row = t / 48;
        int tri = ci / 3, p = ci % 3;
        int base = tri * 12 + p * (p + 1);   // 0, 2, 6
        int dep  = 2 * (p + 1);              // 2, 4, 6
        const float* rp = Ls + row * LPITCH + base;
        float s = 0.f;
        for (int qq = 0; qq < dep; qq++) s += rp[qq];
        g_conj[(size_t)(by * BM + row) * CDIM + bx * 48 + ci] =
            fast_tanh(s - (float)dep + 1.5f);
    }
}

// ---------------------------------------------------------------- finalize
#define RB 16

__global__ __launch_bounds__(256)
void finalize_kernel(const float* __restrict__ x,
                     const float* __restrict__ sigma,
                     float* __restrict__ out)
{
    __shared__ float xs[RB][KDIM];
    __shared__ float xn[RB];
    __shared__ float red[8];

    const int tid = threadIdx.x;
    const int f   = tid;
    const int r0  = blockIdx.x * RB;

    for (int i = tid; i < RB * KDIM; i += 256) {
        int r = i >> 9, k = i & (KDIM - 1);
        xs[r][k] = x[(size_t)(r0 + r) * KDIM + k];
    }
    __syncthreads();

    if (tid < RB) {
        float s = 0.f;
        for (int k = 0; k < KDIM; k++) s += xs[tid][k] * xs[tid][k];
        xn[tid] = s;
    }

    float acc[RB];
#pragma unroll
    for (int r = 0; r < RB; r++) acc[r] = 0.f;
    float mn = 0.f;
    for (int k4 = 0; k4 < KDIM; k4 += 4) {
        float m0 = g_muT[(k4 + 0) * FDIM + f];
        float m1 = g_muT[(k4 + 1) * FDIM + f];
        float m2 = g_muT[(k4 + 2) * FDIM + f];
        float m3 = g_muT[(k4 + 3) * FDIM + f];
        mn = fmaf(m0, m0, mn); mn = fmaf(m1, m1, mn);
        mn = fmaf(m2, m2, mn); mn = fmaf(m3, m3, mn);
#pragma unroll
        for (int r = 0; r < RB; r++) {
            float4 xv = *(const float4*)&xs[r][k4];
            float a = acc[r];
            a = fmaf(xv.x, m0, a);
            a = fmaf(xv.y, m1, a);
            a = fmaf(xv.z, m2, a);
            a = fmaf(xv.w, m3, a);
            acc[r] = a;
        }
    }
    __syncthreads();

    const float sig   = sigma[f];
    const float inv2s = 0.5f / (sig * sig);
    const int   g     = f >> 6;
    const int   nconj = 6 + 3 * g;
    const int   cstart = 96 * g * (g + 3) + (f & 63) * nconj;
    const int   lane = tid & 31, warp = tid >> 5;

    for (int r = 0; r < RB; r++) {
        const float* cp = g_conj + (size_t)(r0 + r) * CDIM + cstart;
        float s = 0.f;
        for (int qd = 0; qd < nconj; qd++) s += cp[qd];
        float dnnf = tanhf(s + (float)nconj - 1.5f);

        float sq = xn[r] - 2.f * acc[r] + mn;
        float logit = 2.0f * expf(-sq * inv2s);
        float e = expf(logit);

        float v = e;
#pragma unroll
        for (int off = 16; off > 0; off >>= 1)
            v += __shfl_xor_sync(0xffffffffu, v, off);
        if (lane == 0) red[warp] = v;
        __syncthreads();
        float tot = red[0] + red[1] + red[2] + red[3] +
                    red[4] + red[5] + red[6] + red[7];
        out[(size_t)(r0 + r) * FDIM + f] = dnnf * (e / tot);
        __syncthreads();
    }
}

// ---------------------------------------------------------------- launch
extern "C" void kernel_launch(void* const* d_in, const int* in_sizes, int n_in,
                              void* d_out, int out_size)
{
    const float* x     = (const float*)d_in[0];
    const float* w     = (const float*)d_in[1];
    const float* msk   = (const float*)d_in[2];
    const float* bias  = (const float*)d_in[3];
    const float* mu    = (const float*)d_in[4];
    const float* sigma = (const float*)d_in[5];
    float* out = (float*)d_out;

    cudaFuncSetAttribute(fused_gemm_dnf_kernel,
                         cudaFuncAttributeMaxDynamicSharedMemorySize, SMEM_NEED);

    prep_mu_kernel<<<(FDIM * KDIM + 255) / 256, 256>>>(mu);
    prep_x_kernel<<<(BATCH * KDIM / 8 + 255) / 256, 256>>>(x);
    {
        dim3 g(LDIM / 32, KDIM / 32);
        dim3 b(32, 32);
        prep_w_kernel<<<g, b>>>(w, msk);
    }
    {
        dim3 grid(LDIM / BN, BATCH / BM);   // (56, 64)
        fused_gemm_dnf_kernel<<<grid, NTHREADS, SMEM_NEED>>>(bias);
    }
    finalize_kernel<<<BATCH / RB, 256>>>(x, sigma, out);
}

// round 5
// speedup vs baseline: 4.5996x; 1.2093x over previous
#include <cuda_runtime.h>
#include <cuda_fp16.h>
#include <cstdint>

// ----------------------------------------------------------------------------
// B = 8192, K = 512, L = 10752 literals, C = 2688 conj, F = 256
// fp16 mma.sync m16n8k16 GEMM; x@muT folded in as 2 extra N-tiles.
// ----------------------------------------------------------------------------
#define BATCH   8192
#define KDIM    512
#define LDIM    10752
#define LDIM2   11136        // + 256 mu rows + 128 zero pad
#define CDIM    2688
#define FDIM    256
#define DPITCH  384          // g_dot row pitch

#define BM 128
#define BN 192
#define BK 64
#define NTHREADS 512
#define STAGE   40960
#define BOFF    16384
#define SM_BIAS (3 * STAGE)
#define SMEM_NEED (SM_BIAS + 768)
#define LPITCH  200
#define NLT     (LDIM / BN)  // 56 literal tiles; bx 56,57 are mu tiles

// scratch
__device__ __half g_A[(size_t)BATCH * KDIM];
__device__ __half g_B[(size_t)LDIM2 * KDIM];
__device__ float g_conj[(size_t)BATCH * CDIM];
__device__ float g_dot[(size_t)BATCH * DPITCH];
__device__ float g_xn[BATCH];
__device__ float g_mn[FDIM];

// ---------------------------------------------------------------- helpers
__device__ __forceinline__ uint32_t smem_u32(const void* p) {
    uint32_t a;
    asm("{ .reg .u64 t; cvta.to.shared.u64 t, %1; cvt.u32.u64 %0, t; }" : "=r"(a) : "l"(p));
    return a;
}
__device__ __forceinline__ void cp16(uint32_t dst, const void* src) {
    asm volatile("cp.async.cg.shared.global [%0], [%1], 16;" :: "r"(dst), "l"(src) : "memory");
}
#define CP_COMMIT() asm volatile("cp.async.commit_group;" ::: "memory")
#define CP_WAIT(n)  asm volatile("cp.async.wait_group %0;" :: "n"(n) : "memory")

__device__ __forceinline__ void ldsm_x4(uint32_t addr, uint32_t r[4]) {
    asm volatile("ldmatrix.sync.aligned.m8n8.x4.shared.b16 {%0,%1,%2,%3}, [%4];"
        : "=r"(r[0]), "=r"(r[1]), "=r"(r[2]), "=r"(r[3]) : "r"(addr));
}
__device__ __forceinline__ void mma_f16(float c[4], const uint32_t a[4],
                                        uint32_t b0, uint32_t b1) {
    asm volatile("mma.sync.aligned.m16n8k16.row.col.f32.f16.f16.f32 "
        "{%0,%1,%2,%3}, {%4,%5,%6,%7}, {%8,%9}, {%0,%1,%2,%3};"
        : "+f"(c[0]), "+f"(c[1]), "+f"(c[2]), "+f"(c[3])
        : "r"(a[0]), "r"(a[1]), "r"(a[2]), "r"(a[3]), "r"(b0), "r"(b1));
}

__device__ __forceinline__ float fast_tanh(float x) {
    float ax = fabsf(x);
    float t;
    asm("ex2.approx.f32 %0, %1;" : "=f"(t) : "f"(ax * -2.885390082f));
    float r = __fdividef(1.f - t, 1.f + t);
    return copysignf(r, x);
}

// ---------------------------------------------------------------- prep kernels
__global__ void prep_x_kernel(const float* __restrict__ x) {
    int i = blockIdx.x * blockDim.x + threadIdx.x;   // BATCH*KDIM/8
    if (i >= BATCH * KDIM / 8) return;
    float4 v0 = *(const float4*)(x + (size_t)i * 8);
    float4 v1 = *(const float4*)(x + (size_t)i * 8 + 4);
    __half2 h[4];
    h[0] = __floats2half2_rn(v0.x, v0.y);
    h[1] = __floats2half2_rn(v0.z, v0.w);
    h[2] = __floats2half2_rn(v1.x, v1.y);
    h[3] = __floats2half2_rn(v1.z, v1.w);
    *(uint4*)(g_A + (size_t)i * 8) = *(uint4*)h;
}

// w,m are [K][L]; g_B[0..LDIM) = fp16(w*m)^T as [L][K]
__global__ void prep_w_kernel(const float* __restrict__ w, const float* __restrict__ m) {
    __shared__ float s[32][33];
    int n0 = blockIdx.x * 32, k0 = blockIdx.y * 32;
    int tx = threadIdx.x, ty = threadIdx.y;
    size_t gi = (size_t)(k0 + ty) * LDIM + n0 + tx;
    s[ty][tx] = w[gi] * m[gi];
    __syncthreads();
    g_B[(size_t)(n0 + ty) * KDIM + k0 + tx] = __float2half_rn(s[tx][ty]);
}

// g_B[LDIM..LDIM+256) = fp16 mu rows, g_mn = ||mu||^2, pad rows zeroed
__global__ void prep_mu_kernel(const float* __restrict__ mu) {
    const int tid = threadIdx.x, wid = tid >> 5, lane = tid & 31;
    if (blockIdx.x < 32) {
        int f = blockIdx.x * 8 + wid;
        const float* src = mu + (size_t)f * KDIM;
        __half* dst = g_B + (size_t)(LDIM + f) * KDIM;
        float sq = 0.f;
#pragma unroll
        for (int j = 0; j < 4; j++) {
            int idx = lane + j * 32;
            float4 v = *(const float4*)(src + idx * 4);
            sq = fmaf(v.x, v.x, sq); sq = fmaf(v.y, v.y, sq);
            sq = fmaf(v.z, v.z, sq); sq = fmaf(v.w, v.w, sq);
            __half2 h0 = __floats2half2_rn(v.x, v.y);
            __half2 h1 = __floats2half2_rn(v.z, v.w);
            uint2 pk = make_uint2(*(uint32_t*)&h0, *(uint32_t*)&h1);
            *(uint2*)(dst + idx * 4) = pk;
        }
#pragma unroll
        for (int off = 16; off > 0; off >>= 1)
            sq += __shfl_xor_sync(0xffffffffu, sq, off);
        if (lane == 0) g_mn[f] = sq;
    } else {
        int row = LDIM + FDIM + (blockIdx.x - 32) * 8 + wid;   // 11008..11135
        __half* dst = g_B + (size_t)row * KDIM;
#pragma unroll
        for (int j = 0; j < 4; j++) {
            int idx = lane + j * 32;
            *(uint2*)(dst + idx * 4) = make_uint2(0u, 0u);
        }
    }
}

// row norms ||x_r||^2 -> g_xn
__global__ void xn_kernel(const float* __restrict__ x) {
    const int tid = threadIdx.x, wid = tid >> 5, lane = tid & 31;
    int row = blockIdx.x * 8 + wid;
    const float* src = x + (size_t)row * KDIM;
    float sq = 0.f;
#pragma unroll
    for (int j = 0; j < 4; j++) {
        int idx = lane + j * 32;
        float4 v = *(const float4*)(src + idx * 4);
        sq = fmaf(v.x, v.x, sq); sq = fmaf(v.y, v.y, sq);
        sq = fmaf(v.z, v.z, sq); sq = fmaf(v.w, v.w, sq);
    }
#pragma unroll
    for (int off = 16; off > 0; off >>= 1)
        sq += __shfl_xor_sync(0xffffffffu, sq, off);
    if (lane == 0) g_xn[row] = sq;
}

// ---------------------------------------------------------------- fused GEMM
__global__ __launch_bounds__(NTHREADS, 1)
void fused_gemm_dnf_kernel(const float* __restrict__ bias) {
    extern __shared__ char smp[];
    const uint32_t sb = smem_u32(smp);

    const int tid = threadIdx.x;
    const int wid = tid >> 5, lane = tid & 31;
    const int bx = blockIdx.x;   // 0..55 literals, 56..57 mu
    const int by = blockIdx.y;
    const int warp_m = wid & 3;
    const int warp_n = wid >> 2;

    float* sbias = (float*)(smp + SM_BIAS);
    if (tid < BN && bx < NLT) sbias[tid] = bias[bx * BN + tid];

    const __half* Ag = g_A + (size_t)(by * BM) * KDIM;
    const __half* Bg = g_B + (size_t)(bx * BN) * KDIM;

    const int r16 = lane & 15, l4 = lane >> 4;
    int am128[2], a7[2];
#pragma unroll
    for (int t = 0; t < 2; t++) {
        int row = warp_m * 32 + t * 16 + r16;
        am128[t] = row * 128; a7[t] = row & 7;
    }
    int bn128[3], b7[3];
#pragma unroll
    for (int i = 0; i < 3; i++) {
        int n = warp_n * 48 + i * 16 + r16;
        bn128[i] = n * 128; b7[i] = n & 7;
    }

    float c[2][6][4];
#pragma unroll
    for (int t = 0; t < 2; t++)
#pragma unroll
        for (int n = 0; n < 6; n++)
#pragma unroll
            for (int e = 0; e < 4; e++) c[t][n][e] = 0.f;

#define ISSUE(kt)                                                              \
    {                                                                          \
        const uint32_t stA = sb + ((kt) % 3) * STAGE;                          \
        _Pragma("unroll")                                                      \
        for (int j = 0; j < 2; j++) {                                          \
            int idx = tid + NTHREADS * j;                                      \
            int row = idx >> 3, ch = idx & 7;                                  \
            cp16(stA + row * 128 + ((ch ^ (row & 7)) << 4),                    \
                 Ag + (size_t)row * KDIM + (kt) * BK + ch * 8);                \
        }                                                                      \
        _Pragma("unroll")                                                      \
        for (int j = 0; j < 3; j++) {                                          \
            int idx = tid + NTHREADS * j;                                      \
            int row = idx >> 3, ch = idx & 7;                                  \
            cp16(stA + BOFF + row * 128 + ((ch ^ (row & 7)) << 4),             \
                 Bg + (size_t)row * KDIM + (kt) * BK + ch * 8);                \
        }                                                                      \
        CP_COMMIT();                                                           \
    }

    ISSUE(0);
    ISSUE(1);

    const int NKT = KDIM / BK;   // 8
    for (int kt = 0; kt < NKT; kt++) {
        CP_WAIT(1);
        __syncthreads();
        if (kt + 2 < NKT) { ISSUE(kt + 2); } else { CP_COMMIT(); }

        const uint32_t sA = sb + (kt % 3) * STAGE;
        const uint32_t sB = sA + BOFF;
#pragma unroll
        for (int ks = 0; ks < 4; ks++) {
            uint32_t af[2][4], bf[3][4];
            const int ch = 2 * ks + l4;
#pragma unroll
            for (int t = 0; t < 2; t++)
                ldsm_x4(sA + am128[t] + ((ch ^ a7[t]) << 4), af[t]);
#pragma unroll
            for (int i = 0; i < 3; i++)
                ldsm_x4(sB + bn128[i] + ((ch ^ b7[i]) << 4), bf[i]);
#pragma unroll
            for (int t = 0; t < 2; t++)
#pragma unroll
                for (int i = 0; i < 3; i++) {
                    mma_f16(c[t][2 * i + 0], af[t], bf[i][0], bf[i][2]);
                    mma_f16(c[t][2 * i + 1], af[t], bf[i][1], bf[i][3]);
                }
        }
    }
#undef ISSUE

    CP_WAIT(0);
    __syncthreads();

    const int g = lane >> 2, cc = lane & 3;

    if (bx >= NLT) {
        // ------------- mu tiles: write raw dots to g_dot -------------
        const int colbase = bx * BN - LDIM;   // 0 or 192
        float* dp = g_dot + (size_t)(by * BM) * DPITCH + colbase;
#pragma unroll
        for (int t = 0; t < 2; t++) {
            int row0 = warp_m * 32 + t * 16 + g;
#pragma unroll
            for (int i = 0; i < 3; i++)
#pragma unroll
                for (int j = 0; j < 2; j++) {
                    int colb = warp_n * 48 + i * 16 + j * 8 + 2 * cc;
                    int nt = 2 * i + j;
                    *(float2*)(dp + (size_t)row0 * DPITCH + colb) =
                        make_float2(c[t][nt][0], c[t][nt][1]);
                    *(float2*)(dp + (size_t)(row0 + 8) * DPITCH + colb) =
                        make_float2(c[t][nt][2], c[t][nt][3]);
                }
        }
        return;
    }

    // ---------------- literal epilogue: tanh + conj reduce ----------------
    float* Ls = (float*)smp;   // [128][LPITCH]
#pragma unroll
    for (int t = 0; t < 2; t++) {
        int row0 = warp_m * 32 + t * 16 + g;
#pragma unroll
        for (int i = 0; i < 3; i++)
#pragma unroll
            for (int j = 0; j < 2; j++) {
                int colb = warp_n * 48 + i * 16 + j * 8 + 2 * cc;
                int nt = 2 * i + j;
                float b0 = sbias[colb], b1 = sbias[colb + 1];
                float2 v0, v1;
                v0.x = fast_tanh(c[t][nt][0] + b0);
                v0.y = fast_tanh(c[t][nt][1] + b1);
                v1.x = fast_tanh(c[t][nt][2] + b0);
                v1.y = fast_tanh(c[t][nt][3] + b1);
                *(float2*)(Ls + row0 * LPITCH + colb) = v0;
                *(float2*)(Ls + (row0 + 8) * LPITCH + colb) = v1;
            }
    }
    __syncthreads();

    for (int t = tid; t < BM * 48; t += NTHREADS) {
        int ci  = t % 48;
        int row = t / 48;
        int tri = ci / 3, p = ci % 3;
        int base = tri * 12 + p * (p + 1);
        int dep  = 2 * (p + 1);
        const float* rp = Ls + row * LPITCH + base;
        float s = 0.f;
        for (int qq = 0; qq < dep; qq++) s += rp[qq];
        g_conj[(size_t)(by * BM + row) * CDIM + bx * 48 + ci] =
            fast_tanh(s - (float)dep + 1.5f);
    }
}

// ---------------------------------------------------------------- finalize
#define RB 4

__global__ __launch_bounds__(256)
void finalize_kernel(const float* __restrict__ sigma, float* __restrict__ out)
{
    __shared__ float sc[RB][CDIM];   // 43 KB
    __shared__ float red[8];
    __shared__ float xns[RB];

    const int tid = threadIdx.x;
    const int f   = tid;
    const int r0  = blockIdx.x * RB;
    const int lane = tid & 31, warp = tid >> 5;

    // stage conj rows
#pragma unroll
    for (int r = 0; r < RB; r++) {
        const float4* src = (const float4*)(g_conj + (size_t)(r0 + r) * CDIM);
        float4* dst = (float4*)sc[r];
        for (int i = tid; i < CDIM / 4; i += 256) dst[i] = src[i];
    }
    if (tid < RB) xns[tid] = g_xn[r0 + tid];

    float dt[RB];
#pragma unroll
    for (int r = 0; r < RB; r++) dt[r] = g_dot[(size_t)(r0 + r) * DPITCH + f];

    const float mn    = g_mn[f];
    const float sig   = sigma[f];
    const float inv2s = 0.5f / (sig * sig);
    const int   g     = f >> 6;
    const int   nconj = 6 + 3 * g;
    const int   cstart = 96 * g * (g + 3) + (f & 63) * nconj;
    __syncthreads();

#pragma unroll
    for (int r = 0; r < RB; r++) {
        float s = 0.f;
        for (int q = 0; q < nconj; q++) s += sc[r][cstart + q];
        float dnnf = fast_tanh(s + (float)nconj - 1.5f);

        float sq = xns[r] - 2.f * dt[r] + mn;
        float logit = 2.0f * expf(-sq * inv2s);
        float e = expf(logit);

        float v = e;
#pragma unroll
        for (int off = 16; off > 0; off >>= 1)
            v += __shfl_xor_sync(0xffffffffu, v, off);
        if (lane == 0) red[warp] = v;
        __syncthreads();
        float tot = red[0] + red[1] + red[2] + red[3] +
                    red[4] + red[5] + red[6] + red[7];
        out[(size_t)(r0 + r) * FDIM + f] = dnnf * (e / tot);
        __syncthreads();
    }
}

// ---------------------------------------------------------------- launch
extern "C" void kernel_launch(void* const* d_in, const int* in_sizes, int n_in,
                              void* d_out, int out_size)
{
    const float* x     = (const float*)d_in[0];
    const float* w     = (const float*)d_in[1];
    const float* msk   = (const float*)d_in[2];
    const float* bias  = (const float*)d_in[3];
    const float* mu    = (const float*)d_in[4];
    const float* sigma = (const float*)d_in[5];
    float* out = (float*)d_out;

    cudaFuncSetAttribute(fused_gemm_dnf_kernel,
                         cudaFuncAttributeMaxDynamicSharedMemorySize, SMEM_NEED);

    prep_x_kernel<<<(BATCH * KDIM / 8 + 255) / 256, 256>>>(x);
    {
        dim3 g(LDIM / 32, KDIM / 32);
        dim3 b(32, 32);
        prep_w_kernel<<<g, b>>>(w, msk);
    }
    prep_mu_kernel<<<48, 256>>>(mu);
    xn_kernel<<<BATCH / 8, 256>>>(x);
    {
        dim3 grid(LDIM2 / BN, BATCH / BM);   // (58, 64)
        fused_gemm_dnf_kernel<<<grid, NTHREADS, SMEM_NEED>>>(bias);
    }
    finalize_kernel<<<BATCH / RB, 256>>>(sigma, out);
}

// round 6
// speedup vs baseline: 4.6617x; 1.0135x over previous
#include <cuda_runtime.h>
#include <cuda_fp16.h>
#include <cstdint>

// ----------------------------------------------------------------------------
// B = 8192, K = 512, L = 10752 literals, C = 2688 conj, F = 256
// fp16 mma.sync m16n8k16 GEMM; x@muT folded in as extra N-tiles.
// 128x96 CTA, 256 threads, 2 CTAs/SM for pipeline overlap.
// ----------------------------------------------------------------------------
#define BATCH   8192
#define KDIM    512
#define LDIM    10752
#define LDIM2   11136        // + 256 mu rows + 128 zero pad
#define CDIM    2688
#define FDIM    256
#define DPITCH  384

#define BM 128
#define BN 96                // 8 triples = 24 conjunctions (triple-aligned)
#define BK 64
#define NTHREADS 256         // 8 warps: 4 (m) x 2 (n), warp tile 32 x 48
#define STAGE   28672        // (128+96)*128 bytes
#define BOFF    16384        // B tile offset within stage (128*128)
#define SM_BIAS (3 * STAGE)  // 86016
#define SMEM_NEED (SM_BIAS + 384)
#define LPITCH  104          // epilogue literal tile pitch (floats)
#define NLT     (LDIM / BN)  // 112 literal tiles; bx 112..115 are mu tiles

// scratch
__device__ __half g_A[(size_t)BATCH * KDIM];
__device__ __half g_B[(size_t)LDIM2 * KDIM];
__device__ float g_conj[(size_t)BATCH * CDIM];
__device__ float g_dot[(size_t)BATCH * DPITCH];
__device__ float g_xn[BATCH];
__device__ float g_mn[FDIM];

// ---------------------------------------------------------------- helpers
__device__ __forceinline__ uint32_t smem_u32(const void* p) {
    uint32_t a;
    asm("{ .reg .u64 t; cvta.to.shared.u64 t, %1; cvt.u32.u64 %0, t; }" : "=r"(a) : "l"(p));
    return a;
}
__device__ __forceinline__ void cp16(uint32_t dst, const void* src) {
    asm volatile("cp.async.cg.shared.global [%0], [%1], 16;" :: "r"(dst), "l"(src) : "memory");
}
#define CP_COMMIT() asm volatile("cp.async.commit_group;" ::: "memory")
#define CP_WAIT(n)  asm volatile("cp.async.wait_group %0;" :: "n"(n) : "memory")

__device__ __forceinline__ void ldsm_x4(uint32_t addr, uint32_t r[4]) {
    asm volatile("ldmatrix.sync.aligned.m8n8.x4.shared.b16 {%0,%1,%2,%3}, [%4];"
        : "=r"(r[0]), "=r"(r[1]), "=r"(r[2]), "=r"(r[3]) : "r"(addr));
}
__device__ __forceinline__ void mma_f16(float c[4], const uint32_t a[4],
                                        uint32_t b0, uint32_t b1) {
    asm volatile("mma.sync.aligned.m16n8k16.row.col.f32.f16.f16.f32 "
        "{%0,%1,%2,%3}, {%4,%5,%6,%7}, {%8,%9}, {%0,%1,%2,%3};"
        : "+f"(c[0]), "+f"(c[1]), "+f"(c[2]), "+f"(c[3])
        : "r"(a[0]), "r"(a[1]), "r"(a[2]), "r"(a[3]), "r"(b0), "r"(b1));
}

__device__ __forceinline__ float fast_tanh(float x) {
    float ax = fabsf(x);
    float t;
    asm("ex2.approx.f32 %0, %1;" : "=f"(t) : "f"(ax * -2.885390082f));
    float r = __fdividef(1.f - t, 1.f + t);
    return copysignf(r, x);
}

// ---------------------------------------------------------------- prep kernels
__global__ void prep_x_kernel(const float* __restrict__ x) {
    int i = blockIdx.x * blockDim.x + threadIdx.x;
    if (i >= BATCH * KDIM / 8) return;
    float4 v0 = *(const float4*)(x + (size_t)i * 8);
    float4 v1 = *(const float4*)(x + (size_t)i * 8 + 4);
    __half2 h[4];
    h[0] = __floats2half2_rn(v0.x, v0.y);
    h[1] = __floats2half2_rn(v0.z, v0.w);
    h[2] = __floats2half2_rn(v1.x, v1.y);
    h[3] = __floats2half2_rn(v1.z, v1.w);
    *(uint4*)(g_A + (size_t)i * 8) = *(uint4*)h;
}

__global__ void prep_w_kernel(const float* __restrict__ w, const float* __restrict__ m) {
    __shared__ float s[32][33];
    int n0 = blockIdx.x * 32, k0 = blockIdx.y * 32;
    int tx = threadIdx.x, ty = threadIdx.y;
    size_t gi = (size_t)(k0 + ty) * LDIM + n0 + tx;
    s[ty][tx] = w[gi] * m[gi];
    __syncthreads();
    g_B[(size_t)(n0 + ty) * KDIM + k0 + tx] = __float2half_rn(s[tx][ty]);
}

__global__ void prep_mu_kernel(const float* __restrict__ mu) {
    const int tid = threadIdx.x, wid = tid >> 5, lane = tid & 31;
    if (blockIdx.x < 32) {
        int f = blockIdx.x * 8 + wid;
        const float* src = mu + (size_t)f * KDIM;
        __half* dst = g_B + (size_t)(LDIM + f) * KDIM;
        float sq = 0.f;
#pragma unroll
        for (int j = 0; j < 4; j++) {
            int idx = lane + j * 32;
            float4 v = *(const float4*)(src + idx * 4);
            sq = fmaf(v.x, v.x, sq); sq = fmaf(v.y, v.y, sq);
            sq = fmaf(v.z, v.z, sq); sq = fmaf(v.w, v.w, sq);
            __half2 h0 = __floats2half2_rn(v.x, v.y);
            __half2 h1 = __floats2half2_rn(v.z, v.w);
            uint2 pk = make_uint2(*(uint32_t*)&h0, *(uint32_t*)&h1);
            *(uint2*)(dst + idx * 4) = pk;
        }
#pragma unroll
        for (int off = 16; off > 0; off >>= 1)
            sq += __shfl_xor_sync(0xffffffffu, sq, off);
        if (lane == 0) g_mn[f] = sq;
    } else {
        int row = LDIM + FDIM + (blockIdx.x - 32) * 8 + wid;
        __half* dst = g_B + (size_t)row * KDIM;
#pragma unroll
        for (int j = 0; j < 4; j++) {
            int idx = lane + j * 32;
            *(uint2*)(dst + idx * 4) = make_uint2(0u, 0u);
        }
    }
}

__global__ void xn_kernel(const float* __restrict__ x) {
    const int tid = threadIdx.x, wid = tid >> 5, lane = tid & 31;
    int row = blockIdx.x * 8 + wid;
    const float* src = x + (size_t)row * KDIM;
    float sq = 0.f;
#pragma unroll
    for (int j = 0; j < 4; j++) {
        int idx = lane + j * 32;
        float4 v = *(const float4*)(src + idx * 4);
        sq = fmaf(v.x, v.x, sq); sq = fmaf(v.y, v.y, sq);
        sq = fmaf(v.z, v.z, sq); sq = fmaf(v.w, v.w, sq);
    }
#pragma unroll
    for (int off = 16; off > 0; off >>= 1)
        sq += __shfl_xor_sync(0xffffffffu, sq, off);
    if (lane == 0) g_xn[row] = sq;
}

// ---------------------------------------------------------------- fused GEMM
__global__ __launch_bounds__(NTHREADS, 2)
void fused_gemm_dnf_kernel(const float* __restrict__ bias) {
    extern __shared__ char smp[];
    const uint32_t sb = smem_u32(smp);

    const int tid = threadIdx.x;
    const int wid = tid >> 5, lane = tid & 31;
    const int bx = blockIdx.x;   // 0..111 literals, 112..115 mu
    const int by = blockIdx.y;
    const int warp_m = wid & 3;  // 4 x 32-row bands
    const int warp_n = wid >> 2; // 2 x 48-col bands

    float* sbias = (float*)(smp + SM_BIAS);
    if (tid < BN && bx < NLT) sbias[tid] = bias[bx * BN + tid];

    const __half* Ag = g_A + (size_t)(by * BM) * KDIM;
    const __half* Bg = g_B + (size_t)(bx * BN) * KDIM;

    const int r16 = lane & 15, l4 = lane >> 4;
    int am128[2], a7[2];
#pragma unroll
    for (int t = 0; t < 2; t++) {
        int row = warp_m * 32 + t * 16 + r16;
        am128[t] = row * 128; a7[t] = row & 7;
    }
    int bn128[3], b7[3];
#pragma unroll
    for (int i = 0; i < 3; i++) {
        int n = warp_n * 48 + i * 16 + r16;
        bn128[i] = n * 128; b7[i] = n & 7;
    }

    float c[2][6][4];
#pragma unroll
    for (int t = 0; t < 2; t++)
#pragma unroll
        for (int n = 0; n < 6; n++)
#pragma unroll
            for (int e = 0; e < 4; e++) c[t][n][e] = 0.f;

    // A: 128 rows x 8 chunks = 1024 ops (4/thread), B: 96 x 8 = 768 (3/thread)
#define ISSUE(kt)                                                              \
    {                                                                          \
        const uint32_t stA = sb + ((kt) % 3) * STAGE;                          \
        _Pragma("unroll")                                                      \
        for (int j = 0; j < 4; j++) {                                          \
            int idx = tid + NTHREADS * j;                                      \
            int row = idx >> 3, ch = idx & 7;                                  \
            cp16(stA + row * 128 + ((ch ^ (row & 7)) << 4),                    \
                 Ag + (size_t)row * KDIM + (kt) * BK + ch * 8);                \
        }                                                                      \
        _Pragma("unroll")                                                      \
        for (int j = 0; j < 3; j++) {                                          \
            int idx = tid + NTHREADS * j;                                      \
            int row = idx >> 3, ch = idx & 7;                                  \
            cp16(stA + BOFF + row * 128 + ((ch ^ (row & 7)) << 4),             \
                 Bg + (size_t)row * KDIM + (kt) * BK + ch * 8);                \
        }                                                                      \
        CP_COMMIT();                                                           \
    }

    ISSUE(0);
    ISSUE(1);

    const int NKT = KDIM / BK;   // 8
    for (int kt = 0; kt < NKT; kt++) {
        CP_WAIT(1);
        __syncthreads();
        if (kt + 2 < NKT) { ISSUE(kt + 2); } else { CP_COMMIT(); }

        const uint32_t sA = sb + (kt % 3) * STAGE;
        const uint32_t sB = sA + BOFF;
#pragma unroll
        for (int ks = 0; ks < 4; ks++) {
            uint32_t af[2][4], bf[3][4];
            const int ch = 2 * ks + l4;
#pragma unroll
            for (int t = 0; t < 2; t++)
                ldsm_x4(sA + am128[t] + ((ch ^ a7[t]) << 4), af[t]);
#pragma unroll
            for (int i = 0; i < 3; i++)
                ldsm_x4(sB + bn128[i] + ((ch ^ b7[i]) << 4), bf[i]);
#pragma unroll
            for (int t = 0; t < 2; t++)
#pragma unroll
                for (int i = 0; i < 3; i++) {
                    mma_f16(c[t][2 * i + 0], af[t], bf[i][0], bf[i][2]);
                    mma_f16(c[t][2 * i + 1], af[t], bf[i][1], bf[i][3]);
                }
        }
    }
#undef ISSUE

    CP_WAIT(0);
    __syncthreads();

    const int g = lane >> 2, cc = lane & 3;

    if (bx >= NLT) {
        // ------------- mu tiles: write raw dots to g_dot -------------
        const int colbase = bx * BN - LDIM;   // 0, 96, 192, 288
        float* dp = g_dot + (size_t)(by * BM) * DPITCH + colbase;
#pragma unroll
        for (int t = 0; t < 2; t++) {
            int row0 = warp_m * 32 + t * 16 + g;
#pragma unroll
            for (int i = 0; i < 3; i++)
#pragma unroll
                for (int j = 0; j < 2; j++) {
                    int colb = warp_n * 48 + i * 16 + j * 8 + 2 * cc;
                    int nt = 2 * i + j;
                    *(float2*)(dp + (size_t)row0 * DPITCH + colb) =
                        make_float2(c[t][nt][0], c[t][nt][1]);
                    *(float2*)(dp + (size_t)(row0 + 8) * DPITCH + colb) =
                        make_float2(c[t][nt][2], c[t][nt][3]);
                }
        }
        return;
    }

    // ---------------- literal epilogue: tanh + conj reduce ----------------
    float* Ls = (float*)smp;   // [128][LPITCH]
#pragma unroll
    for (int t = 0; t < 2; t++) {
        int row0 = warp_m * 32 + t * 16 + g;
#pragma unroll
        for (int i = 0; i < 3; i++)
#pragma unroll
            for (int j = 0; j < 2; j++) {
                int colb = warp_n * 48 + i * 16 + j * 8 + 2 * cc;
                int nt = 2 * i + j;
                float b0 = sbias[colb], b1 = sbias[colb + 1];
                float2 v0, v1;
                v0.x = fast_tanh(c[t][nt][0] + b0);
                v0.y = fast_tanh(c[t][nt][1] + b1);
                v1.x = fast_tanh(c[t][nt][2] + b0);
                v1.y = fast_tanh(c[t][nt][3] + b1);
                *(float2*)(Ls + row0 * LPITCH + colb) = v0;
                *(float2*)(Ls + (row0 + 8) * LPITCH + colb) = v1;
            }
    }
    __syncthreads();

    // 128 rows x 24 conj = 3072 tasks
    for (int t = tid; t < BM * 24; t += NTHREADS) {
        int ci  = t % 24;
        int row = t / 24;
        int tri = ci / 3, p = ci % 3;
        int base = tri * 12 + p * (p + 1);   // 0, 2, 6
        int dep  = 2 * (p + 1);              // 2, 4, 6
        const float* rp = Ls + row * LPITCH + base;
        float s = 0.f;
        for (int qq = 0; qq < dep; qq++) s += rp[qq];
        g_conj[(size_t)(by * BM + row) * CDIM + bx * 24 + ci] =
            fast_tanh(s - (float)dep + 1.5f);
    }
}

// ---------------------------------------------------------------- finalize
#define RB 4

__global__ __launch_bounds__(256)
void finalize_kernel(const float* __restrict__ sigma, float* __restrict__ out)
{
    __shared__ float sc[RB][CDIM];
    __shared__ float red[8];
    __shared__ float xns[RB];

    const int tid = threadIdx.x;
    const int f   = tid;
    const int r0  = blockIdx.x * RB;
    const int lane = tid & 31, warp = tid >> 5;

#pragma unroll
    for (int r = 0; r < RB; r++) {
        const float4* src = (const float4*)(g_conj + (size_t)(r0 + r) * CDIM);
        float4* dst = (float4*)sc[r];
        for (int i = tid; i < CDIM / 4; i += 256) dst[i] = src[i];
    }
    if (tid < RB) xns[tid] = g_xn[r0 + tid];

    float dt[RB];
#pragma unroll
    for (int r = 0; r < RB; r++) dt[r] = g_dot[(size_t)(r0 + r) * DPITCH + f];

    const float mn    = g_mn[f];
    const float sig   = sigma[f];
    const float inv2s = 0.5f / (sig * sig);
    const int   g     = f >> 6;
    const int   nconj = 6 + 3 * g;
    const int   cstart = 96 * g * (g + 3) + (f & 63) * nconj;
    __syncthreads();

#pragma unroll
    for (int r = 0; r < RB; r++) {
        float s = 0.f;
        for (int q = 0; q < nconj; q++) s += sc[r][cstart + q];
        float dnnf = fast_tanh(s + (float)nconj - 1.5f);

        float sq = xns[r] - 2.f * dt[r] + mn;
        float logit = 2.0f * expf(-sq * inv2s);
        float e = expf(logit);

        float v = e;
#pragma unroll
        for (int off = 16; off > 0; off >>= 1)
            v += __shfl_xor_sync(0xffffffffu, v, off);
        if (lane == 0) red[warp] = v;
        __syncthreads();
        float tot = red[0] + red[1] + red[2] + red[3] +
                    red[4] + red[5] + red[6] + red[7];
        out[(size_t)(r0 + r) * FDIM + f] = dnnf * (e / tot);
        __syncthreads();
    }
}

// ---------------------------------------------------------------- launch
extern "C" void kernel_launch(void* const* d_in, const int* in_sizes, int n_in,
                              void* d_out, int out_size)
{
    const float* x     = (const float*)d_in[0];
    const float* w     = (const float*)d_in[1];
    const float* msk   = (const float*)d_in[2];
    const float* bias  = (const float*)d_in[3];
    const float* mu    = (const float*)d_in[4];
    const float* sigma = (const float*)d_in[5];
    float* out = (float*)d_out;

    cudaFuncSetAttribute(fused_gemm_dnf_kernel,
                         cudaFuncAttributeMaxDynamicSharedMemorySize, SMEM_NEED);

    prep_x_kernel<<<(BATCH * KDIM / 8 + 255) / 256, 256>>>(x);
    {
        dim3 g(LDIM / 32, KDIM / 32);
        dim3 b(32, 32);
        prep_w_kernel<<<g, b>>>(w, msk);
    }
    prep_mu_kernel<<<48, 256>>>(mu);
    xn_kernel<<<BATCH / 8, 256>>>(x);
    {
        dim3 grid(LDIM2 / BN, BATCH / BM);   // (116, 64)
        fused_gemm_dnf_kernel<<<grid, NTHREADS, SMEM_NEED>>>(bias);
    }
    finalize_kernel<<<BATCH / RB, 256>>>(sigma, out);
}